// round 4
// baseline (speedup 1.0000x reference)
#include <cuda_runtime.h>
#include <cuda_bf16.h>
#include <math.h>

// Problem constants
// inputs: [4,64,64,256] -> X [16384,256]; Wq/Wk [256,32], Wv/Wo [256,256]
#define NTOK   16384      // total tokens (B*H*W)
#define NSEQ   4096       // tokens per batch
#define CH     256        // channels F
#define DQK    32         // q/k dim
#define NQKV   320        // 32+32+256
#define KT     32         // keys per attention tile

// ---------------- device scratch (no allocations allowed) ----------------
// NOTE: these are referenced ONLY from device code (never passed as kernel
// args from host — host-side symbol address is the host shadow, not the
// device buffer, and ATS on GB300 makes that a silent wrong-memory write).
__device__ float g_q[NTOK * DQK];       // 2 MB
__device__ float g_k[NTOK * DQK];       // 2 MB
__device__ float g_v[NTOK * CH];        // 16 MB
__device__ float g_att[NTOK * CH];      // 16 MB
__device__ float g_wqkv[CH * NQKV];     // 320 KB
__device__ float g_bias[NQKV];

// ---------------- prep: concat weights + biases ----------------
__global__ void prep_kernel(const float* __restrict__ Wq, const float* __restrict__ bq,
                            const float* __restrict__ Wk, const float* __restrict__ bk,
                            const float* __restrict__ Wv, const float* __restrict__ bv) {
    int i = blockIdx.x * blockDim.x + threadIdx.x;
    if (i < CH * NQKV) {
        int d = i / NQKV, c = i % NQKV;
        float val;
        if (c < 32)       val = Wq[d * 32 + c];
        else if (c < 64)  val = Wk[d * 32 + (c - 32)];
        else              val = Wv[d * 256 + (c - 64)];
        g_wqkv[i] = val;
    } else if (i < CH * NQKV + NQKV) {
        int c = i - CH * NQKV;
        g_bias[c] = (c < 32) ? bq[c] : (c < 64) ? bk[c - 32] : bv[c - 64];
    }
}

// ---------------- gemm: qkv projection ----------------
// C[16384,320] = relu(X[16384,256] @ Wc[256,320] + bias), routed to q/k/v
__global__ __launch_bounds__(256) void gemm_qkv_kernel(
    const float* __restrict__ X) {
    __shared__ float As[16][68];   // transposed A tile [k][m]
    __shared__ float Bs[16][68];   // B tile [k][n]
    int t = threadIdx.x;
    int m0 = blockIdx.x * 64;
    int n0 = blockIdx.y * 64;
    int tr = t >> 4, tc = t & 15;
    int arow = t >> 2, aseg = t & 3;
    int brow = t >> 4, bseg = t & 15;

    float acc[4][4];
#pragma unroll
    for (int i = 0; i < 4; i++)
#pragma unroll
        for (int j = 0; j < 4; j++) acc[i][j] = 0.f;

    for (int k0 = 0; k0 < CH; k0 += 16) {
        float4 av = *(const float4*)&X[(m0 + arow) * CH + k0 + aseg * 4];
        float4 bv = *(const float4*)&g_wqkv[(k0 + brow) * NQKV + n0 + bseg * 4];
        __syncthreads();
        As[aseg * 4 + 0][arow] = av.x;
        As[aseg * 4 + 1][arow] = av.y;
        As[aseg * 4 + 2][arow] = av.z;
        As[aseg * 4 + 3][arow] = av.w;
        *(float4*)&Bs[brow][bseg * 4] = bv;
        __syncthreads();
#pragma unroll
        for (int kk = 0; kk < 16; kk++) {
            float4 a = *(const float4*)&As[kk][tr * 4];
            float4 b = *(const float4*)&Bs[kk][tc * 4];
            acc[0][0] += a.x * b.x; acc[0][1] += a.x * b.y; acc[0][2] += a.x * b.z; acc[0][3] += a.x * b.w;
            acc[1][0] += a.y * b.x; acc[1][1] += a.y * b.y; acc[1][2] += a.y * b.z; acc[1][3] += a.y * b.w;
            acc[2][0] += a.z * b.x; acc[2][1] += a.z * b.y; acc[2][2] += a.z * b.z; acc[2][3] += a.z * b.w;
            acc[3][0] += a.w * b.x; acc[3][1] += a.w * b.y; acc[3][2] += a.w * b.z; acc[3][3] += a.w * b.w;
        }
    }

    int c = n0 + tc * 4;
    float b0 = g_bias[c + 0], b1 = g_bias[c + 1], b2 = g_bias[c + 2], b3 = g_bias[c + 3];
#pragma unroll
    for (int i = 0; i < 4; i++) {
        int gr = m0 + tr * 4 + i;
        float4 o;
        o.x = fmaxf(acc[i][0] + b0, 0.f);
        o.y = fmaxf(acc[i][1] + b1, 0.f);
        o.z = fmaxf(acc[i][2] + b2, 0.f);
        o.w = fmaxf(acc[i][3] + b3, 0.f);
        if (c < 32)       *(float4*)&g_q[gr * DQK + c]        = o;
        else if (c < 64)  *(float4*)&g_k[gr * DQK + (c - 32)] = o;
        else              *(float4*)&g_v[gr * CH  + (c - 64)] = o;
    }
}

// ---------------- fused two-pass attention ----------------
// Per CTA: 32 queries x full 256 channels; 32-key tiles.
// Pass A: exact global row max (K only). Pass B: exp(s-m), AV + l (no rescale).
// Static smem: 47104 bytes (< 48KB, no opt-in needed).
__global__ __launch_bounds__(256) void attn_kernel() {
    __shared__ float qs[32 * 33];       // Q tile  [r][d]
    __shared__ float ks[KT * 32];       // K tile  [j][d]
    __shared__ float ss[KT * 33];       // P tile  [j][r] (transposed)
    __shared__ float vs[KT * 260];      // V tile  [j][c] (stride 260)
    __shared__ float red[8 * 32];       // cross-warp reduce [w][r]
    __shared__ float m_row[32];
    __shared__ float linv_s[32];

    int t = threadIdx.x;
    int lane = t & 31;
    int w = t >> 5;
    int batch = blockIdx.x >> 7;    // 128 q-tiles per batch
    int qtile = blockIdx.x & 127;
    int qrow0 = batch * NSEQ + qtile * 32;
    int krow0 = batch * NSEQ;

    // stage Q tile
    for (int i = t; i < 32 * 32; i += 256) {
        int r = i >> 5, d = i & 31;
        qs[r * 33 + d] = g_q[(qrow0 + r) * DQK + d];
    }
    __syncthreads();

    float qreg[32];
#pragma unroll
    for (int d = 0; d < 32; d++) qreg[d] = qs[lane * 33 + d];

    // ---------- Pass A: global row max ----------
    float pmax = -1e30f;
    for (int kt = 0; kt < NSEQ / KT; kt++) {
        __syncthreads();   // prev tile's scores done reading ks
        int kr0 = krow0 + kt * KT;
        {   // K tile: 32 rows x 8 float4 = 256 float4 (1 per thread)
            int j = t >> 3, dseg = t & 7;
            *(float4*)&ks[j * 32 + dseg * 4] =
                *(const float4*)&g_k[(kr0 + j) * DQK + dseg * 4];
        }
        __syncthreads();
#pragma unroll
        for (int jj = 0; jj < 4; jj++) {
            int j = w + jj * 8;
            const float* kp = ks + j * 32;
            float s = 0.f;
#pragma unroll
            for (int dd = 0; dd < 8; dd++) {
                float4 kv = *(const float4*)(kp + dd * 4);  // warp-broadcast
                s += qreg[dd * 4 + 0] * kv.x + qreg[dd * 4 + 1] * kv.y
                   + qreg[dd * 4 + 2] * kv.z + qreg[dd * 4 + 3] * kv.w;
            }
            pmax = fmaxf(pmax, s);
        }
    }
    __syncthreads();
    red[w * 32 + lane] = pmax;
    __syncthreads();
    if (t < 32) {
        float m = red[t];
#pragma unroll
        for (int k = 1; k < 8; k++) m = fmaxf(m, red[k * 32 + t]);
        m_row[t] = m;
    }
    __syncthreads();
    float mrow = m_row[lane];   // per-row max (row = lane)

    // ---------- Pass B: exp + AV + l ----------
    float acc[32];
#pragma unroll
    for (int c = 0; c < 32; c++) acc[c] = 0.f;
    float lpart = 0.f;

    for (int kt = 0; kt < NSEQ / KT; kt++) {
        __syncthreads();   // prev AV done reading ks/vs/ss
        int kr0 = krow0 + kt * KT;
        {   // K tile
            int j = t >> 3, dseg = t & 7;
            *(float4*)&ks[j * 32 + dseg * 4] =
                *(const float4*)&g_k[(kr0 + j) * DQK + dseg * 4];
        }
        for (int i = t; i < KT * 64; i += 256) {   // V tile: 2048 float4
            int j = i >> 6, cseg = i & 63;
            *(float4*)&vs[j * 260 + cseg * 4] =
                *(const float4*)&g_v[(kr0 + j) * CH + cseg * 4];
        }
        __syncthreads();

        // scores + exp: thread handles row=lane, j in {w, w+8, w+16, w+24}
#pragma unroll
        for (int jj = 0; jj < 4; jj++) {
            int j = w + jj * 8;
            const float* kp = ks + j * 32;
            float s = 0.f;
#pragma unroll
            for (int dd = 0; dd < 8; dd++) {
                float4 kv = *(const float4*)(kp + dd * 4);
                s += qreg[dd * 4 + 0] * kv.x + qreg[dd * 4 + 1] * kv.y
                   + qreg[dd * 4 + 2] * kv.z + qreg[dd * 4 + 3] * kv.w;
            }
            float p = __expf(s - mrow);
            ss[j * 33 + lane] = p;
            lpart += p;
        }
        __syncthreads();

        // AV: thread: row=lane, cols w*32 .. w*32+31
        {
            const float* vbase = vs + w * 32;
#pragma unroll 4
            for (int j = 0; j < KT; j++) {
                float p = ss[j * 33 + lane];
                const float* vp = vbase + j * 260;
#pragma unroll
                for (int cc = 0; cc < 8; cc++) {
                    float4 vv = *(const float4*)(vp + cc * 4);  // warp-broadcast
                    acc[cc * 4 + 0] += p * vv.x;
                    acc[cc * 4 + 1] += p * vv.y;
                    acc[cc * 4 + 2] += p * vv.z;
                    acc[cc * 4 + 3] += p * vv.w;
                }
            }
        }
    }

    // reduce l across warps
    __syncthreads();
    red[w * 32 + lane] = lpart;
    __syncthreads();
    if (t < 32) {
        float l = red[t];
#pragma unroll
        for (int k = 1; k < 8; k++) l += red[k * 32 + t];
        linv_s[t] = 1.f / l;
    }
    __syncthreads();

    // normalize + transpose-stage + coalesced store (reuse vs as [32][257])
    float inv = linv_s[lane];
    float* ts = vs;
#pragma unroll
    for (int c = 0; c < 32; c++) ts[lane * 257 + w * 32 + c] = acc[c] * inv;
    __syncthreads();
    for (int i = t; i < 32 * 256; i += 256) {
        int r = i >> 8, c = i & 255;
        g_att[(qrow0 + r) * CH + c] = ts[r * 257 + c];
    }
}

// ---------------- gemm: output projection + relu + residual ----------------
__global__ __launch_bounds__(256) void gemm_out_kernel(
    const float* __restrict__ inputs, const float* __restrict__ Wo,
    const float* __restrict__ bo, float* __restrict__ out) {
    __shared__ float As[16][68];
    __shared__ float Bs[16][68];
    int t = threadIdx.x;
    int m0 = blockIdx.x * 64;
    int n0 = blockIdx.y * 64;
    int tr = t >> 4, tc = t & 15;
    int arow = t >> 2, aseg = t & 3;
    int brow = t >> 4, bseg = t & 15;

    float acc[4][4];
#pragma unroll
    for (int i = 0; i < 4; i++)
#pragma unroll
        for (int j = 0; j < 4; j++) acc[i][j] = 0.f;

    for (int k0 = 0; k0 < CH; k0 += 16) {
        float4 av = *(const float4*)&g_att[(m0 + arow) * CH + k0 + aseg * 4];
        float4 bv = *(const float4*)&Wo[(k0 + brow) * CH + n0 + bseg * 4];
        __syncthreads();
        As[aseg * 4 + 0][arow] = av.x;
        As[aseg * 4 + 1][arow] = av.y;
        As[aseg * 4 + 2][arow] = av.z;
        As[aseg * 4 + 3][arow] = av.w;
        *(float4*)&Bs[brow][bseg * 4] = bv;
        __syncthreads();
#pragma unroll
        for (int kk = 0; kk < 16; kk++) {
            float4 a = *(const float4*)&As[kk][tr * 4];
            float4 b = *(const float4*)&Bs[kk][tc * 4];
            acc[0][0] += a.x * b.x; acc[0][1] += a.x * b.y; acc[0][2] += a.x * b.z; acc[0][3] += a.x * b.w;
            acc[1][0] += a.y * b.x; acc[1][1] += a.y * b.y; acc[1][2] += a.y * b.z; acc[1][3] += a.y * b.w;
            acc[2][0] += a.z * b.x; acc[2][1] += a.z * b.y; acc[2][2] += a.z * b.z; acc[2][3] += a.z * b.w;
            acc[3][0] += a.w * b.x; acc[3][1] += a.w * b.y; acc[3][2] += a.w * b.z; acc[3][3] += a.w * b.w;
        }
    }

    int c = n0 + tc * 4;
    float b0 = bo[c + 0], b1 = bo[c + 1], b2 = bo[c + 2], b3 = bo[c + 3];
#pragma unroll
    for (int i = 0; i < 4; i++) {
        int gr = m0 + tr * 4 + i;
        float4 iv = *(const float4*)&inputs[gr * CH + c];
        float4 o;
        o.x = iv.x + fmaxf(acc[i][0] + b0, 0.f);
        o.y = iv.y + fmaxf(acc[i][1] + b1, 0.f);
        o.z = iv.z + fmaxf(acc[i][2] + b2, 0.f);
        o.w = iv.w + fmaxf(acc[i][3] + b3, 0.f);
        *(float4*)&out[gr * CH + c] = o;
    }
}

// ---------------- launch ----------------
extern "C" void kernel_launch(void* const* d_in, const int* in_sizes, int n_in,
                              void* d_out, int out_size) {
    const float* inputs = (const float*)d_in[0];
    const float* Wq = (const float*)d_in[1];
    const float* bq = (const float*)d_in[2];
    const float* Wk = (const float*)d_in[3];
    const float* bk = (const float*)d_in[4];
    const float* Wv = (const float*)d_in[5];
    const float* bv = (const float*)d_in[6];
    const float* Wo = (const float*)d_in[7];
    const float* bo = (const float*)d_in[8];
    float* out = (float*)d_out;

    int prep_elems = CH * NQKV + NQKV;
    prep_kernel<<<(prep_elems + 255) / 256, 256>>>(Wq, bq, Wk, bk, Wv, bv);

    gemm_qkv_kernel<<<dim3(NTOK / 64, NQKV / 64), 256>>>(inputs);

    attn_kernel<<<4 * (NSEQ / 32), 256>>>();

    gemm_out_kernel<<<dim3(NTOK / 64, CH / 64), 256>>>(inputs, Wo, bo, out);
}

// round 5
// speedup vs baseline: 1.3467x; 1.3467x over previous
#include <cuda_runtime.h>
#include <cuda_bf16.h>
#include <math.h>

// Problem constants
// inputs: [4,64,64,256] -> X [16384,256]; Wq/Wk [256,32], Wv/Wo [256,256]
#define NTOK   16384      // total tokens (B*H*W)
#define NSEQ   4096       // tokens per batch
#define CH     256        // channels F
#define DQK    32         // q/k dim
#define NQKV   320        // 32+32+256
#define KT     32         // keys per attention tile

// ---------------- f32x2 packed-FMA helpers (sm_103a) ----------------
typedef unsigned long long u64;
__device__ __forceinline__ u64 pk2(float a, float b) {
    u64 r; asm("mov.b64 %0, {%1,%2};" : "=l"(r) : "f"(a), "f"(b)); return r;
}
__device__ __forceinline__ u64 fma2(u64 a, u64 b, u64 c) {
    u64 d; asm("fma.rn.f32x2 %0, %1, %2, %3;" : "=l"(d) : "l"(a), "l"(b), "l"(c)); return d;
}
__device__ __forceinline__ void upk2(u64 v, float& lo, float& hi) {
    asm("mov.b64 {%0,%1}, %2;" : "=f"(lo), "=f"(hi) : "l"(v));
}

// ---------------- device scratch (no allocations allowed) ----------------
// Referenced ONLY from device code (host-side symbol is the host shadow;
// ATS on GB300 makes passing it as a kernel arg a silent wrong-memory write).
__device__ float g_q[NTOK * DQK];       // 2 MB
__device__ float g_k[NTOK * DQK];       // 2 MB
__device__ float g_v[NTOK * CH];        // 16 MB
__device__ float g_att[NTOK * CH];      // 16 MB
__device__ float g_wqkv[CH * NQKV];     // 320 KB
__device__ float g_bias[NQKV];

// ---------------- prep: concat weights + biases ----------------
__global__ void prep_kernel(const float* __restrict__ Wq, const float* __restrict__ bq,
                            const float* __restrict__ Wk, const float* __restrict__ bk,
                            const float* __restrict__ Wv, const float* __restrict__ bv) {
    int i = blockIdx.x * blockDim.x + threadIdx.x;
    if (i < CH * NQKV) {
        int d = i / NQKV, c = i % NQKV;
        float val;
        if (c < 32)       val = Wq[d * 32 + c];
        else if (c < 64)  val = Wk[d * 32 + (c - 32)];
        else              val = Wv[d * 256 + (c - 64)];
        g_wqkv[i] = val;
    } else if (i < CH * NQKV + NQKV) {
        int c = i - CH * NQKV;
        g_bias[c] = (c < 32) ? bq[c] : (c < 64) ? bk[c - 32] : bv[c - 64];
    }
}

// ---------------- gemm: qkv projection ----------------
__global__ __launch_bounds__(256) void gemm_qkv_kernel(
    const float* __restrict__ X) {
    __shared__ float As[16][68];   // transposed A tile [k][m]
    __shared__ float Bs[16][68];   // B tile [k][n]
    int t = threadIdx.x;
    int m0 = blockIdx.x * 64;
    int n0 = blockIdx.y * 64;
    int tr = t >> 4, tc = t & 15;
    int arow = t >> 2, aseg = t & 3;
    int brow = t >> 4, bseg = t & 15;

    float acc[4][4];
#pragma unroll
    for (int i = 0; i < 4; i++)
#pragma unroll
        for (int j = 0; j < 4; j++) acc[i][j] = 0.f;

    for (int k0 = 0; k0 < CH; k0 += 16) {
        float4 av = *(const float4*)&X[(m0 + arow) * CH + k0 + aseg * 4];
        float4 bv = *(const float4*)&g_wqkv[(k0 + brow) * NQKV + n0 + bseg * 4];
        __syncthreads();
        As[aseg * 4 + 0][arow] = av.x;
        As[aseg * 4 + 1][arow] = av.y;
        As[aseg * 4 + 2][arow] = av.z;
        As[aseg * 4 + 3][arow] = av.w;
        *(float4*)&Bs[brow][bseg * 4] = bv;
        __syncthreads();
#pragma unroll
        for (int kk = 0; kk < 16; kk++) {
            float4 a = *(const float4*)&As[kk][tr * 4];
            float4 b = *(const float4*)&Bs[kk][tc * 4];
            acc[0][0] += a.x * b.x; acc[0][1] += a.x * b.y; acc[0][2] += a.x * b.z; acc[0][3] += a.x * b.w;
            acc[1][0] += a.y * b.x; acc[1][1] += a.y * b.y; acc[1][2] += a.y * b.z; acc[1][3] += a.y * b.w;
            acc[2][0] += a.z * b.x; acc[2][1] += a.z * b.y; acc[2][2] += a.z * b.z; acc[2][3] += a.z * b.w;
            acc[3][0] += a.w * b.x; acc[3][1] += a.w * b.y; acc[3][2] += a.w * b.z; acc[3][3] += a.w * b.w;
        }
    }

    int c = n0 + tc * 4;
    float b0 = g_bias[c + 0], b1 = g_bias[c + 1], b2 = g_bias[c + 2], b3 = g_bias[c + 3];
#pragma unroll
    for (int i = 0; i < 4; i++) {
        int gr = m0 + tr * 4 + i;
        float4 o;
        o.x = fmaxf(acc[i][0] + b0, 0.f);
        o.y = fmaxf(acc[i][1] + b1, 0.f);
        o.z = fmaxf(acc[i][2] + b2, 0.f);
        o.w = fmaxf(acc[i][3] + b3, 0.f);
        if (c < 32)       *(float4*)&g_q[gr * DQK + c]        = o;
        else if (c < 64)  *(float4*)&g_k[gr * DQK + (c - 32)] = o;
        else              *(float4*)&g_v[gr * CH  + (c - 64)] = o;
    }
}

// ---------------- fused two-pass attention (f32x2 packed math) ----------------
// Per CTA: 32 queries x 256 channels; 32-key tiles.
// Pass A: exact global row max (QK only). Pass B: exp(s-m), AV + l (no rescale).
// AV thread map: 2 query rows x 16 channels -> 8+8 FFMA2 per key.
// Static smem: 47232 bytes (< 48KB, no opt-in needed).
__global__ __launch_bounds__(256) void attn_kernel() {
    __shared__ __align__(16) float vs[KT * 260];  // V tile [j][c] (stride 260)
    __shared__ __align__(16) float qs[32 * 33];   // Q tile [r][d]
    __shared__ __align__(16) float ks[KT * 32];   // K tile [j][d]
    __shared__ __align__(16) float ss[KT * 34];   // P tile [j][r] (stride 34: float2-aligned row pairs)
    __shared__ float red[8 * 32];                 // cross-warp reduce [w][r]
    __shared__ float m_row[32];
    __shared__ float linv_s[32];

    int t = threadIdx.x;
    int lane = t & 31;
    int w = t >> 5;
    int rg = lane & 15;                 // row-pair group: rows 2rg, 2rg+1
    int cg = (w << 1) | (lane >> 4);    // channel group: channels cg*16..cg*16+15
    int batch = blockIdx.x >> 7;        // 128 q-tiles per batch
    int qtile = blockIdx.x & 127;
    int qrow0 = batch * NSEQ + qtile * 32;
    int krow0 = batch * NSEQ;

    // stage Q tile
    for (int i = t; i < 32 * 32; i += 256) {
        int r = i >> 5, d = i & 31;
        qs[r * 33 + d] = g_q[(qrow0 + r) * DQK + d];
    }
    __syncthreads();

    // q packed as 16 f32x2 (row = lane, for score phases)
    u64 q2[16];
#pragma unroll
    for (int d = 0; d < 16; d++)
        q2[d] = pk2(qs[lane * 33 + 2 * d], qs[lane * 33 + 2 * d + 1]);

    // ---------- Pass A: global row max ----------
    float pmax = -1e30f;
    for (int kt = 0; kt < NSEQ / KT; kt++) {
        __syncthreads();   // prev tile's reads done before overwriting ks
        int kr0 = krow0 + kt * KT;
        {   // K tile: 32 rows x 8 float4 (1 per thread)
            int j = t >> 3, dseg = t & 7;
            *(float4*)&ks[j * 32 + dseg * 4] =
                *(const float4*)&g_k[(kr0 + j) * DQK + dseg * 4];
        }
        __syncthreads();
#pragma unroll
        for (int jj = 0; jj < 4; jj++) {
            int j = w + jj * 8;
            const ulonglong2* kp = (const ulonglong2*)(ks + j * 32);
            u64 s2 = 0;   // packed 0.0f,0.0f
#pragma unroll
            for (int dd = 0; dd < 8; dd++) {
                ulonglong2 kv = kp[dd];   // 4 floats as 2 f32x2 (warp-broadcast)
                s2 = fma2(q2[dd * 2 + 0], kv.x, s2);
                s2 = fma2(q2[dd * 2 + 1], kv.y, s2);
            }
            float slo, shi; upk2(s2, slo, shi);
            pmax = fmaxf(pmax, slo + shi);
        }
    }
    __syncthreads();
    red[w * 32 + lane] = pmax;
    __syncthreads();
    if (t < 32) {
        float m = red[t];
#pragma unroll
        for (int k = 1; k < 8; k++) m = fmaxf(m, red[k * 32 + t]);
        m_row[t] = m;
    }
    __syncthreads();
    float mrow = m_row[lane];   // per-row max (row = lane)

    // ---------- Pass B: exp + AV + l ----------
    u64 acc2a[8], acc2b[8];     // rows 2rg / 2rg+1, channels cg*16.. (8 f32x2 each)
#pragma unroll
    for (int i = 0; i < 8; i++) { acc2a[i] = 0; acc2b[i] = 0; }
    float lpart = 0.f;

    for (int kt = 0; kt < NSEQ / KT; kt++) {
        __syncthreads();   // prev AV done reading ks/vs/ss
        int kr0 = krow0 + kt * KT;
        {   // K tile
            int j = t >> 3, dseg = t & 7;
            *(float4*)&ks[j * 32 + dseg * 4] =
                *(const float4*)&g_k[(kr0 + j) * DQK + dseg * 4];
        }
        for (int i = t; i < KT * 64; i += 256) {   // V tile: 2048 float4
            int j = i >> 6, cseg = i & 63;
            *(float4*)&vs[j * 260 + cseg * 4] =
                *(const float4*)&g_v[(kr0 + j) * CH + cseg * 4];
        }
        __syncthreads();

        // scores + exp: row = lane, j in {w, w+8, w+16, w+24}
#pragma unroll
        for (int jj = 0; jj < 4; jj++) {
            int j = w + jj * 8;
            const ulonglong2* kp = (const ulonglong2*)(ks + j * 32);
            u64 s2 = 0;
#pragma unroll
            for (int dd = 0; dd < 8; dd++) {
                ulonglong2 kv = kp[dd];
                s2 = fma2(q2[dd * 2 + 0], kv.x, s2);
                s2 = fma2(q2[dd * 2 + 1], kv.y, s2);
            }
            float slo, shi; upk2(s2, slo, shi);
            float p = __expf(slo + shi - mrow);
            ss[j * 34 + lane] = p;
            lpart += p;
        }
        __syncthreads();

        // AV: rows 2rg,2rg+1 x channels cg*16..cg*16+15
        {
            const float* vb = vs + cg * 16;
#pragma unroll 8
            for (int j = 0; j < KT; j++) {
                float2 pp = *(const float2*)&ss[j * 34 + 2 * rg];
                u64 p2a = pk2(pp.x, pp.x);
                u64 p2b = pk2(pp.y, pp.y);
                const ulonglong2* vp = (const ulonglong2*)(vb + j * 260);
#pragma unroll
                for (int cc = 0; cc < 4; cc++) {
                    ulonglong2 vv = vp[cc];   // 4 channels as 2 f32x2
                    acc2a[cc * 2 + 0] = fma2(p2a, vv.x, acc2a[cc * 2 + 0]);
                    acc2a[cc * 2 + 1] = fma2(p2a, vv.y, acc2a[cc * 2 + 1]);
                    acc2b[cc * 2 + 0] = fma2(p2b, vv.x, acc2b[cc * 2 + 0]);
                    acc2b[cc * 2 + 1] = fma2(p2b, vv.y, acc2b[cc * 2 + 1]);
                }
            }
        }
    }

    // reduce l across warps (lpart is per-row, row = lane)
    __syncthreads();
    red[w * 32 + lane] = lpart;
    __syncthreads();
    if (t < 32) {
        float l = red[t];
#pragma unroll
        for (int k = 1; k < 8; k++) l += red[k * 32 + t];
        linv_s[t] = 1.f / l;
    }
    __syncthreads();

    // normalize + transpose-stage + coalesced store (reuse vs as [32][257])
    float inva = linv_s[2 * rg];
    float invb = linv_s[2 * rg + 1];
    float* ts = vs;
#pragma unroll
    for (int i = 0; i < 8; i++) {
        float a0, a1, b0, b1;
        upk2(acc2a[i], a0, a1);
        upk2(acc2b[i], b0, b1);
        ts[(2 * rg + 0) * 257 + cg * 16 + 2 * i + 0] = a0 * inva;
        ts[(2 * rg + 0) * 257 + cg * 16 + 2 * i + 1] = a1 * inva;
        ts[(2 * rg + 1) * 257 + cg * 16 + 2 * i + 0] = b0 * invb;
        ts[(2 * rg + 1) * 257 + cg * 16 + 2 * i + 1] = b1 * invb;
    }
    __syncthreads();
    for (int i = t; i < 32 * 256; i += 256) {
        int r = i >> 8, c = i & 255;
        g_att[(qrow0 + r) * CH + c] = ts[r * 257 + c];
    }
}

// ---------------- gemm: output projection + relu + residual ----------------
__global__ __launch_bounds__(256) void gemm_out_kernel(
    const float* __restrict__ inputs, const float* __restrict__ Wo,
    const float* __restrict__ bo, float* __restrict__ out) {
    __shared__ float As[16][68];
    __shared__ float Bs[16][68];
    int t = threadIdx.x;
    int m0 = blockIdx.x * 64;
    int n0 = blockIdx.y * 64;
    int tr = t >> 4, tc = t & 15;
    int arow = t >> 2, aseg = t & 3;
    int brow = t >> 4, bseg = t & 15;

    float acc[4][4];
#pragma unroll
    for (int i = 0; i < 4; i++)
#pragma unroll
        for (int j = 0; j < 4; j++) acc[i][j] = 0.f;

    for (int k0 = 0; k0 < CH; k0 += 16) {
        float4 av = *(const float4*)&g_att[(m0 + arow) * CH + k0 + aseg * 4];
        float4 bv = *(const float4*)&Wo[(k0 + brow) * CH + n0 + bseg * 4];
        __syncthreads();
        As[aseg * 4 + 0][arow] = av.x;
        As[aseg * 4 + 1][arow] = av.y;
        As[aseg * 4 + 2][arow] = av.z;
        As[aseg * 4 + 3][arow] = av.w;
        *(float4*)&Bs[brow][bseg * 4] = bv;
        __syncthreads();
#pragma unroll
        for (int kk = 0; kk < 16; kk++) {
            float4 a = *(const float4*)&As[kk][tr * 4];
            float4 b = *(const float4*)&Bs[kk][tc * 4];
            acc[0][0] += a.x * b.x; acc[0][1] += a.x * b.y; acc[0][2] += a.x * b.z; acc[0][3] += a.x * b.w;
            acc[1][0] += a.y * b.x; acc[1][1] += a.y * b.y; acc[1][2] += a.y * b.z; acc[1][3] += a.y * b.w;
            acc[2][0] += a.z * b.x; acc[2][1] += a.z * b.y; acc[2][2] += a.z * b.z; acc[2][3] += a.z * b.w;
            acc[3][0] += a.w * b.x; acc[3][1] += a.w * b.y; acc[3][2] += a.w * b.z; acc[3][3] += a.w * b.w;
        }
    }

    int c = n0 + tc * 4;
    float b0 = bo[c + 0], b1 = bo[c + 1], b2 = bo[c + 2], b3 = bo[c + 3];
#pragma unroll
    for (int i = 0; i < 4; i++) {
        int gr = m0 + tr * 4 + i;
        float4 iv = *(const float4*)&inputs[gr * CH + c];
        float4 o;
        o.x = iv.x + fmaxf(acc[i][0] + b0, 0.f);
        o.y = iv.y + fmaxf(acc[i][1] + b1, 0.f);
        o.z = iv.z + fmaxf(acc[i][2] + b2, 0.f);
        o.w = iv.w + fmaxf(acc[i][3] + b3, 0.f);
        *(float4*)&out[gr * CH + c] = o;
    }
}

// ---------------- launch ----------------
extern "C" void kernel_launch(void* const* d_in, const int* in_sizes, int n_in,
                              void* d_out, int out_size) {
    const float* inputs = (const float*)d_in[0];
    const float* Wq = (const float*)d_in[1];
    const float* bq = (const float*)d_in[2];
    const float* Wk = (const float*)d_in[3];
    const float* bk = (const float*)d_in[4];
    const float* Wv = (const float*)d_in[5];
    const float* bv = (const float*)d_in[6];
    const float* Wo = (const float*)d_in[7];
    const float* bo = (const float*)d_in[8];
    float* out = (float*)d_out;

    int prep_elems = CH * NQKV + NQKV;
    prep_kernel<<<(prep_elems + 255) / 256, 256>>>(Wq, bq, Wk, bk, Wv, bv);

    gemm_qkv_kernel<<<dim3(NTOK / 64, NQKV / 64), 256>>>(inputs);

    attn_kernel<<<4 * (NSEQ / 32), 256>>>();

    gemm_out_kernel<<<dim3(NTOK / 64, CH / 64), 256>>>(inputs, Wo, bo, out);
}